// round 5
// baseline (speedup 1.0000x reference)
#include <cuda_runtime.h>
#include <cstddef>

// SpecialFlatten == batched float2 transpose: in2 [B, R, CP] -> out2 [B, CP, R]
// B=32, R=2048, C=512, CP=256.
//
// R4 experiment: identical to R3's v5 (128R x 32CP tile, 512 threads,
// even/odd smem planes + permuted columns, zero bank conflicts) with the
// ONE change of removing the __ldcs/__stcs streaming hints — isolating
// whether R3's regression came from the hints or the tall tile.

namespace {
constexpr int B   = 32;
constexpr int R   = 2048;
constexpr int CP  = 256;           // float2 columns
constexpr int C4  = CP / 2;        // 128 float4 per input row
constexpr int R4  = R / 2;         // 1024 float4 per output row
constexpr int TILE_R = 128;        // float2 rows per tile
constexpr int TILE_C = 32;         // float2 cols per tile (= 16 float4)
constexpr int NPAIR  = TILE_R / 2; // 64 row pairs
}

__global__ __launch_bounds__(512)
void special_flatten_v7(const float4* __restrict__ in,
                        float4* __restrict__ out) {
    __shared__ float2 sA[NPAIR][33];   // even rows (row 2m -> sA[m])
    __shared__ float2 sB[NPAIR][33];   // odd rows  (row 2m+1 -> sB[m])

    const int b = blockIdx.z;
    const float4* __restrict__ inb  = in  + (size_t)b * R * C4;
    float4* __restrict__       outb = out + (size_t)b * CP * R4;

    const int tid = threadIdx.x;

    // ---- Load phase: 4x LDG.128 per thread, STS.64 lane-linear ----
    {
        const int tx = tid & 15;                 // float4 col within tile (0..15)
        const int ty = tid >> 4;                 // 0..31
        const int c4 = blockIdx.x * (TILE_C / 2) + tx;
        const int r0 = blockIdx.y * TILE_R;
#pragma unroll
        for (int k = 0; k < 2; k++) {
            const int m = ty + 32 * k;           // row pair 0..63
            const float4 v0 = inb[(size_t)(r0 + 2 * m    ) * C4 + c4];
            const float4 v1 = inb[(size_t)(r0 + 2 * m + 1) * C4 + c4];
            // logical cols 2tx, 2tx+1 -> storage cols tx, tx+16 (permuted)
            sA[m][tx]      = make_float2(v0.x, v0.y);
            sA[m][tx + 16] = make_float2(v0.z, v0.w);
            sB[m][tx]      = make_float2(v1.x, v1.y);
            sB[m][tx + 16] = make_float2(v1.z, v1.w);
        }
    }

    __syncthreads();

    // ---- Store phase: LDS.64 lane-linear, 4x STG.128 per thread ----
    {
        const int sx = tid & 63;                 // float4 R-index within tile (0..63)
        const int sy = tid >> 6;                 // 0..7
        const int r4 = blockIdx.y * (TILE_R / 2) + sx;
#pragma unroll
        for (int n = 0; n < 4; n++) {
            const int c  = sy + 8 * n;           // CP-local col 0..31
            const int sc = (c >> 1) + (c & 1) * 16;   // permuted storage col
            const float2 a  = sA[sx][sc];        // in2[2*sx][c]
            const float2 bb = sB[sx][sc];        // in2[2*sx+1][c]
            outb[(size_t)(blockIdx.x * TILE_C + c) * R4 + r4] =
                make_float4(a.x, a.y, bb.x, bb.y);
        }
    }
}

extern "C" void kernel_launch(void* const* d_in, const int* in_sizes, int n_in,
                              void* d_out, int out_size) {
    const float4* in  = (const float4*)d_in[0];
    float4*       out = (float4*)d_out;

    dim3 block(512, 1, 1);
    dim3 grid(CP / TILE_C, R / TILE_R, B);   // (8, 16, 32) = 4096 blocks
    special_flatten_v7<<<grid, block>>>(in, out);
}

// round 6
// speedup vs baseline: 1.0006x; 1.0006x over previous
#include <cuda_runtime.h>
#include <cstddef>

// SpecialFlatten == batched float2 transpose: in2 [B, R, CP] -> out2 [B, CP, R]
// B=32, R=2048, C=512, CP=256.
//
// v8: WIDER tile, same thread shape as the proven v4/v6 (256 threads, 8 warps).
// Tile 64R x 64CP (float2 units). Even/odd smem row planes + permuted column
// layout ([32][65], storage col = (c>>1) + (c&1)*32) => every STS.64/LDS.64 is
// lane-linear (bank 2*lane), zero conflicts. 8x LDG.128 + 8x STG.128 per thread.

namespace {
constexpr int B   = 32;
constexpr int R   = 2048;
constexpr int CP  = 256;           // float2 columns
constexpr int C4  = CP / 2;        // 128 float4 per input row
constexpr int R4  = R / 2;         // 1024 float4 per output row
constexpr int TILE_R = 64;         // float2 rows per tile (32 pairs)
constexpr int TILE_C = 64;         // float2 cols per tile (= 32 float4)
}

__global__ __launch_bounds__(256)
void special_flatten_v8(const float4* __restrict__ in,
                        float4* __restrict__ out) {
    __shared__ float2 sA[32][65];   // even rows (row 2m -> sA[m])
    __shared__ float2 sB[32][65];   // odd rows  (row 2m+1 -> sB[m])

    const int b = blockIdx.z;
    const float4* __restrict__ inb  = in  + (size_t)b * R * C4;
    float4* __restrict__       outb = out + (size_t)b * CP * R4;

    const int tid = threadIdx.x;

    // ---- Load phase: 8x LDG.128 per thread, STS.64 lane-linear ----
    {
        const int tx = tid & 31;                 // float4 col within tile (0..31)
        const int ty = tid >> 5;                 // warp id (0..7)
        const int c4 = blockIdx.x * (TILE_C / 2) + tx;
        const int r0 = blockIdx.y * TILE_R;
#pragma unroll
        for (int k = 0; k < 4; k++) {
            const int m = ty + 8 * k;            // row pair 0..31
            const float4 v0 = inb[(size_t)(r0 + 2 * m    ) * C4 + c4];
            const float4 v1 = inb[(size_t)(r0 + 2 * m + 1) * C4 + c4];
            // logical float2 cols 2tx, 2tx+1 -> storage cols tx, tx+32
            sA[m][tx]      = make_float2(v0.x, v0.y);
            sA[m][tx + 32] = make_float2(v0.z, v0.w);
            sB[m][tx]      = make_float2(v1.x, v1.y);
            sB[m][tx + 32] = make_float2(v1.z, v1.w);
        }
    }

    __syncthreads();

    // ---- Store phase: LDS.64 lane-linear, 8x STG.128 per thread ----
    {
        const int sx = tid & 31;                 // float4 R-index within tile (0..31)
        const int sy = tid >> 5;                 // warp id (0..7)
        const int r4 = blockIdx.y * (TILE_R / 2) + sx;
#pragma unroll
        for (int n = 0; n < 8; n++) {
            const int c  = sy + 8 * n;           // CP-local col 0..63
            const int sc = (c >> 1) + (c & 1) * 32;   // permuted storage col
            const float2 a  = sA[sx][sc];        // in2[2*sx][c]
            const float2 bb = sB[sx][sc];        // in2[2*sx+1][c]
            outb[(size_t)(blockIdx.x * TILE_C + c) * R4 + r4] =
                make_float4(a.x, a.y, bb.x, bb.y);
        }
    }
}

extern "C" void kernel_launch(void* const* d_in, const int* in_sizes, int n_in,
                              void* d_out, int out_size) {
    const float4* in  = (const float4*)d_in[0];
    float4*       out = (float4*)d_out;

    dim3 block(256, 1, 1);
    dim3 grid(CP / TILE_C, R / TILE_R, B);   // (4, 32, 32) = 4096 blocks
    special_flatten_v8<<<grid, block>>>(in, out);
}

// round 7
// speedup vs baseline: 1.1007x; 1.1000x over previous
#include <cuda_runtime.h>
#include <cstddef>

// SpecialFlatten == batched float2 transpose: in2 [B, R, CP] -> out2 [B, CP, R]
// B=32, R=2048, C=512, CP=256.
//
// v9: software-pipelined double buffer. Per-stage tile 32R x 32CP (float2),
// 256 threads, 2x LDG.128/thread per stage, NT=4 stages per CTA along R.
// Double-buffered even/odd smem planes ([2][16][33] x2 = 16.9 KB, same as v4).
// Next-stage LDGs issue before the current store phase -> each CTA keeps read
// and write streams concurrently active. All smem ops lane-linear, 0 conflicts.

namespace {
constexpr int B   = 32;
constexpr int R   = 2048;
constexpr int CP  = 256;           // float2 columns
constexpr int C4  = CP / 2;        // 128 float4 per input row
constexpr int R4  = R / 2;         // 1024 float4 per output row
constexpr int TILE_R = 32;         // float2 rows per stage (16 pairs)
constexpr int TILE_C = 32;         // float2 cols per tile (= 16 float4)
constexpr int NT  = 4;             // stages per CTA (covers 128 rows)
}

__global__ __launch_bounds__(256)
void special_flatten_v9(const float4* __restrict__ in,
                        float4* __restrict__ out) {
    __shared__ float2 sA[2][16][33];   // even rows (row 2m -> sA[buf][m])
    __shared__ float2 sB[2][16][33];   // odd rows

    const int b = blockIdx.z;
    const float4* __restrict__ inb  = in  + (size_t)b * R * C4;
    float4* __restrict__       outb = out + (size_t)b * CP * R4;

    const int tid = threadIdx.x;
    const int tx  = tid & 15;          // float4 col within tile (0..15)
    const int ty  = tid >> 4;          // row pair (0..15)
    const int ctile  = blockIdx.x;
    const int c4     = ctile * (TILE_C / 2) + tx;
    const int r0base = blockIdx.y * (TILE_R * NT);

    // ---- Prologue: load stage 0 into buffer 0 ----
    {
        const float4 v0 = inb[(size_t)(r0base + 2 * ty    ) * C4 + c4];
        const float4 v1 = inb[(size_t)(r0base + 2 * ty + 1) * C4 + c4];
        sA[0][ty][tx]      = make_float2(v0.x, v0.y);
        sA[0][ty][tx + 16] = make_float2(v0.z, v0.w);
        sB[0][ty][tx]      = make_float2(v1.x, v1.y);
        sB[0][ty][tx + 16] = make_float2(v1.z, v1.w);
    }
    __syncthreads();

#pragma unroll
    for (int t = 0; t < NT; t++) {
        // ---- Prefetch stage t+1 (LDG issued before store phase) ----
        float4 w0, w1;
        if (t + 1 < NT) {
            const int r0 = r0base + (t + 1) * TILE_R;
            w0 = inb[(size_t)(r0 + 2 * ty    ) * C4 + c4];
            w1 = inb[(size_t)(r0 + 2 * ty + 1) * C4 + c4];
        }

        // ---- Store stage t from buf[t&1]: LDS.64 lane-linear, 2x STG.128 ----
        {
            const int cur = t & 1;
            const int sx  = tid & 15;          // float4 R-index in stage (0..15)
            const int sy  = tid >> 4;          // 0..15
            const int r4  = (r0base + t * TILE_R) / 2 + sx;
#pragma unroll
            for (int n = 0; n < 2; n++) {
                const int c  = sy + 16 * n;    // CP-local col 0..31
                const int sc = (c >> 1) + (c & 1) * 16;
                const float2 a  = sA[cur][sx][sc];   // in2[2*sx][c]
                const float2 bb = sB[cur][sx][sc];   // in2[2*sx+1][c]
                outb[(size_t)(ctile * TILE_C + c) * R4 + r4] =
                    make_float4(a.x, a.y, bb.x, bb.y);
            }
        }

        // ---- Commit prefetch into the other buffer ----
        if (t + 1 < NT) {
            const int nxt = (t + 1) & 1;
            sA[nxt][ty][tx]      = make_float2(w0.x, w0.y);
            sA[nxt][ty][tx + 16] = make_float2(w0.z, w0.w);
            sB[nxt][ty][tx]      = make_float2(w1.x, w1.y);
            sB[nxt][ty][tx + 16] = make_float2(w1.z, w1.w);
            __syncthreads();
        }
    }
}

extern "C" void kernel_launch(void* const* d_in, const int* in_sizes, int n_in,
                              void* d_out, int out_size) {
    const float4* in  = (const float4*)d_in[0];
    float4*       out = (float4*)d_out;

    dim3 block(256, 1, 1);
    dim3 grid(CP / TILE_C, R / (TILE_R * NT), B);   // (8, 16, 32) = 4096 blocks
    special_flatten_v9<<<grid, block>>>(in, out);
}